// round 7
// baseline (speedup 1.0000x reference)
#include <cuda_runtime.h>
#include <cuda_bf16.h>
#include <math_constants.h>
#include <cstdint>

#define B_  4
#define H_  16
#define S_  2048
#define DM  1024
#define DK  64
#define M_  (B_*S_)

// ---------------- scratch (device globals; no allocation allowed) ----------
__device__ float g_Q[M_*DM];
__device__ float g_K[M_*DM];
__device__ float g_V[M_*DM];
__device__ float g_attn[M_*DM];

__device__ __forceinline__ uint32_t smem_u32(const void* p) {
    uint32_t a;
    asm("{ .reg .u64 t; cvta.to.shared.u64 t, %1; cvt.u32.u64 %0, t; }"
        : "=r"(a) : "l"(p));
    return a;
}
__device__ __forceinline__ void ldsm_x4(uint32_t r[4], uint32_t addr) {
    asm volatile("ldmatrix.sync.aligned.m8n8.x4.shared.b16 {%0,%1,%2,%3}, [%4];"
        : "=r"(r[0]), "=r"(r[1]), "=r"(r[2]), "=r"(r[3]) : "r"(addr));
}
__device__ __forceinline__ void ldsm_x2(uint32_t r[2], uint32_t addr) {
    asm volatile("ldmatrix.sync.aligned.m8n8.x2.shared.b16 {%0,%1}, [%2];"
        : "=r"(r[0]), "=r"(r[1]) : "r"(addr));
}
__device__ __forceinline__ void ldsm_x2t(uint32_t r[2], uint32_t addr) {
    asm volatile("ldmatrix.sync.aligned.m8n8.x2.trans.shared.b16 {%0,%1}, [%2];"
        : "=r"(r[0]), "=r"(r[1]) : "r"(addr));
}
__device__ __forceinline__ void mma16816(float d[4], const uint32_t a[4],
                                         const uint32_t b[2]) {
    asm volatile(
        "mma.sync.aligned.m16n8k16.row.col.f32.bf16.bf16.f32 "
        "{%0,%1,%2,%3}, {%4,%5,%6,%7}, {%8,%9}, {%0,%1,%2,%3};"
        : "+f"(d[0]), "+f"(d[1]), "+f"(d[2]), "+f"(d[3])
        : "r"(a[0]), "r"(a[1]), "r"(a[2]), "r"(a[3]), "r"(b[0]), "r"(b[1]));
}

__device__ __forceinline__ uint32_t pk_bf2(float x, float y) {
    __nv_bfloat162 h = __floats2bfloat162_rn(x, y);
    return *reinterpret_cast<uint32_t*>(&h);
}
__device__ __forceinline__ void split2(float x, float y,
                                       uint32_t& hi, uint32_t& lo) {
    __nv_bfloat162 h2 = __floats2bfloat162_rn(x, y);
    float2 hf = __bfloat1622float2(h2);
    __nv_bfloat162 l2 = __floats2bfloat162_rn(x - hf.x, y - hf.y);
    hi = *reinterpret_cast<uint32_t*>(&h2);
    lo = *reinterpret_cast<uint32_t*>(&l2);
}
__device__ __forceinline__ void split8(float4 v0, float4 v1,
                                       uint4& hi, uint4& lo) {
    float h[8], f[8] = {v0.x, v0.y, v0.z, v0.w, v1.x, v1.y, v1.z, v1.w};
    float l[8];
    #pragma unroll
    for (int i = 0; i < 8; i++) {
        __nv_bfloat16 hb = __float2bfloat16_rn(f[i]);
        h[i] = __bfloat162float(hb);
        l[i] = f[i] - h[i];
    }
    hi = make_uint4(pk_bf2(h[0],h[1]), pk_bf2(h[2],h[3]),
                    pk_bf2(h[4],h[5]), pk_bf2(h[6],h[7]));
    lo = make_uint4(pk_bf2(l[0],l[1]), pk_bf2(l[2],l[3]),
                    pk_bf2(l[4],l[5]), pk_bf2(l[6],l[7]));
}

// Fast exp2 on FMA pipe (no MUFU).
__device__ __forceinline__ float exp2fast(float x) {
    x = fmaxf(x, -126.0f);
    float z = x + 12582912.0f;
    int   k = __float_as_int(z) - 0x4B400000;
    float f = x - (z - 12582912.0f);
    float p = fmaf(0.00133336f, f, 0.00961813f);
    p = fmaf(p, f, 0.05550411f);
    p = fmaf(p, f, 0.24022651f);
    p = fmaf(p, f, 0.69314718f);
    p = fmaf(p, f, 1.0f);
    return __int_as_float(__float_as_int(p) + (k << 23));
}

// ---------------------------------------------------------------------------
// Tensor-core GEMM (R4 verbatim — best measured): out = A*W^T + bias
// ---------------------------------------------------------------------------
#define TSTR   80
#define TILEB  (128*TSTR)
#define AT_HI  0
#define AT_LO  TILEB
#define WT_HI  (2*TILEB)
#define WT_LO  (3*TILEB)

__global__ __launch_bounds__(256)
void gemm_mma(const float* __restrict__ A, const float* __restrict__ W,
              const float* __restrict__ bias, float* __restrict__ out,
              int split_heads)
{
    __shared__ __align__(16) char sm[4*TILEB];
    const uint32_t sb = smem_u32(sm);

    const int tid = threadIdx.x;
    const int m0  = blockIdx.y << 7;
    const int n0  = blockIdx.x << 7;
    const int warp = tid >> 5;
    const int lane = tid & 31;
    const int wm = (warp >> 2) * 64;
    const int wn = (warp & 3) * 32;

    const uint32_t arow = (lane & 15) * TSTR + (lane >> 4) * 16;
    const uint32_t brow = (lane & 7) * TSTR + ((lane >> 3) & 1) * 16;

    const int lrow = tid >> 1;
    const int lcg  = (tid & 1) * 16;
    const float* Ag = A + (size_t)(m0 + lrow) * DM + lcg;
    const float* Wg = W + (size_t)(n0 + lrow) * DM + lcg;
    char* smArow = sm + lrow * TSTR + lcg * 2;
    char* smWrow = smArow;

    float acc[4][4][4];
    #pragma unroll
    for (int i = 0; i < 4; i++)
        #pragma unroll
        for (int j = 0; j < 4; j++)
            #pragma unroll
            for (int r = 0; r < 4; r++) acc[i][j][r] = 0.f;

    float4 ra0 = *(const float4*)(Ag);      float4 ra1 = *(const float4*)(Ag + 4);
    float4 ra2 = *(const float4*)(Ag + 8);  float4 ra3 = *(const float4*)(Ag + 12);
    float4 rw0 = *(const float4*)(Wg);      float4 rw1 = *(const float4*)(Wg + 4);
    float4 rw2 = *(const float4*)(Wg + 8);  float4 rw3 = *(const float4*)(Wg + 12);

    for (int c = 0; c < DM / 32; ++c) {
        __syncthreads();
        uint4 hi, lo;
        split8(ra0, ra1, hi, lo);
        *(uint4*)(smArow + AT_HI)      = hi;  *(uint4*)(smArow + AT_LO)      = lo;
        split8(ra2, ra3, hi, lo);
        *(uint4*)(smArow + AT_HI + 16) = hi;  *(uint4*)(smArow + AT_LO + 16) = lo;
        split8(rw0, rw1, hi, lo);
        *(uint4*)(smWrow + WT_HI)      = hi;  *(uint4*)(smWrow + WT_LO)      = lo;
        split8(rw2, rw3, hi, lo);
        *(uint4*)(smWrow + WT_HI + 16) = hi;  *(uint4*)(smWrow + WT_LO + 16) = lo;
        __syncthreads();

        if (c < DM / 32 - 1) {
            const float* An = Ag + (c + 1) * 32;
            const float* Wn = Wg + (c + 1) * 32;
            ra0 = *(const float4*)(An);      ra1 = *(const float4*)(An + 4);
            ra2 = *(const float4*)(An + 8);  ra3 = *(const float4*)(An + 12);
            rw0 = *(const float4*)(Wn);      rw1 = *(const float4*)(Wn + 4);
            rw2 = *(const float4*)(Wn + 8);  rw3 = *(const float4*)(Wn + 12);
        }

        #pragma unroll
        for (int pass = 0; pass < 3; ++pass) {
            const uint32_t aoff = (pass == 1) ? AT_LO : AT_HI;
            const uint32_t boff = (pass == 2) ? WT_LO : WT_HI;
            #pragma unroll
            for (int ks = 0; ks < 2; ++ks) {
                uint32_t af[4][4], bf[4][2];
                #pragma unroll
                for (int mt = 0; mt < 4; ++mt)
                    ldsm_x4(af[mt], sb + aoff + (wm + mt*16) * TSTR
                                        + ks * 32 + arow);
                #pragma unroll
                for (int nt = 0; nt < 4; ++nt)
                    ldsm_x2(bf[nt], sb + boff + (wn + nt*8) * TSTR
                                        + ks * 32 + brow);
                #pragma unroll
                for (int mt = 0; mt < 4; ++mt)
                    #pragma unroll
                    for (int nt = 0; nt < 4; ++nt)
                        mma16816(acc[mt][nt], af[mt], bf[nt]);
            }
        }
    }

    #pragma unroll
    for (int mt = 0; mt < 4; ++mt) {
        #pragma unroll
        for (int nt = 0; nt < 4; ++nt) {
            const int col = n0 + wn + nt*8 + (lane & 3) * 2;
            const float2 bv = *(const float2*)(bias + col);
            #pragma unroll
            for (int half = 0; half < 2; ++half) {
                const int row = m0 + wm + mt*16 + (lane >> 2) + half * 8;
                float2 o2 = make_float2(acc[mt][nt][2*half]   + bv.x,
                                        acc[mt][nt][2*half+1] + bv.y);
                size_t idx;
                if (split_heads) {
                    const int head = col >> 6;
                    const int bi = row >> 11, si = row & (S_ - 1);
                    idx = (((size_t)(bi * H_ + head)) * S_ + si) * DK + (col & 63);
                } else {
                    idx = (size_t)row * DM + col;
                }
                *(float2*)(out + idx) = o2;
            }
        }
    }
}

// ---------------------------------------------------------------------------
// Tensor-core flash attention — 64-q-row CTAs, 128 threads, 54KB smem
// (3 CTAs/SM -> softmax/loader of one CTA overlaps MMA of others).
// Per-warp math identical to R4; Q fragments hoisted out of the k-loop.
// ---------------------------------------------------------------------------
#define ASTR   144
#define A_QHI  0
#define A_QLO  9216
#define A_KHI  18432
#define A_KLO  27648
#define A_VHI  36864
#define A_VLO  46080
#define ATTN_SMEM 55296

extern __shared__ char dynsm[];

__global__ __launch_bounds__(128)
void attn_mma(const float* __restrict__ Qh, const float* __restrict__ Kh,
              const float* __restrict__ Vh, float* __restrict__ outA)
{
    const uint32_t sb = smem_u32(dynsm);
    const int tid = threadIdx.x;
    const int lane = tid & 31;
    const int warp = tid >> 5;
    const int qt = blockIdx.x, h = blockIdx.y, b = blockIdx.z;

    const size_t bh = (size_t)(b * H_ + h) * S_ * DK;
    const float* Qb = Qh + bh + (size_t)qt * 64 * DK;
    const float* Kb = Kh + bh;
    const float* Vb = Vh + bh;

    const int row = tid >> 1;          // 0..63
    const int c0  = (tid & 1) * 32;    // float col 0 / 32

    // ---- Q: load, scale, hi/lo split, store to smem ----
    {
        const float* g = Qb + row * DK + c0;
        char* s = dynsm + row * ASTR + c0 * 2;
        const float sc = 0.1803368801f;     // 0.125 * log2(e)
        #pragma unroll
        for (int j = 0; j < 4; j++) {
            float4 v0 = *(const float4*)(g + j*8);
            float4 v1 = *(const float4*)(g + j*8 + 4);
            v0.x *= sc; v0.y *= sc; v0.z *= sc; v0.w *= sc;
            v1.x *= sc; v1.y *= sc; v1.z *= sc; v1.w *= sc;
            uint4 hi, lo; split8(v0, v1, hi, lo);
            *(uint4*)(s + A_QHI + j*16) = hi;
            *(uint4*)(s + A_QLO + j*16) = lo;
        }
    }
    __syncthreads();

    // ---- hoist Q fragments (loop-invariant) ----
    uint32_t qah[4][4], qal[4][4];
    {
        const uint32_t qrow = (warp * 16 + (lane & 15)) * ASTR + (lane >> 4) * 16;
        #pragma unroll
        for (int ks = 0; ks < 4; ++ks) {
            ldsm_x4(qah[ks], sb + A_QHI + qrow + ks * 32);
            ldsm_x4(qal[ks], sb + A_QLO + qrow + ks * 32);
        }
    }

    float m0 = -1e30f, m1 = -1e30f, l0 = 0.f, l1 = 0.f;
    float o[8][4];
    #pragma unroll
    for (int nf = 0; nf < 8; nf++)
        #pragma unroll
        for (int r = 0; r < 4; r++) o[nf][r] = 0.f;

    char* kvs = dynsm + row * ASTR + c0 * 2;
    const uint32_t kbrow = (lane & 7) * ASTR + ((lane >> 3) & 1) * 16;
    const uint32_t vbrow = (lane & 15) * ASTR;

    for (int kt = 0; kt < S_ / 64; ++kt) {
        const float* kg = Kb + (size_t)(kt * 64 + row) * DK + c0;
        const float* vg = Vb + (size_t)(kt * 64 + row) * DK + c0;
        __syncthreads();       // prev iteration's smem consumers done
        #pragma unroll
        for (int j = 0; j < 2; j++) {
            float4 k0 = *(const float4*)(kg + j*16);
            float4 k1 = *(const float4*)(kg + j*16 + 4);
            float4 k2 = *(const float4*)(kg + j*16 + 8);
            float4 k3 = *(const float4*)(kg + j*16 + 12);
            uint4 hi, lo;
            split8(k0, k1, hi, lo);
            *(uint4*)(kvs + A_KHI + j*32)      = hi;
            *(uint4*)(kvs + A_KLO + j*32)      = lo;
            split8(k2, k3, hi, lo);
            *(uint4*)(kvs + A_KHI + j*32 + 16) = hi;
            *(uint4*)(kvs + A_KLO + j*32 + 16) = lo;
        }
        #pragma unroll
        for (int j = 0; j < 2; j++) {
            float4 v0 = *(const float4*)(vg + j*16);
            float4 v1 = *(const float4*)(vg + j*16 + 4);
            float4 v2 = *(const float4*)(vg + j*16 + 8);
            float4 v3 = *(const float4*)(vg + j*16 + 12);
            uint4 hi, lo;
            split8(v0, v1, hi, lo);
            *(uint4*)(kvs + A_VHI + j*32)      = hi;
            *(uint4*)(kvs + A_VLO + j*32)      = lo;
            split8(v2, v3, hi, lo);
            *(uint4*)(kvs + A_VHI + j*32 + 16) = hi;
            *(uint4*)(kvs + A_VLO + j*32 + 16) = lo;
        }
        __syncthreads();

        // ---- scores S[16q x 64k] = Q K^T (3-pass hi/lo) ----
        float sacc[8][4];
        #pragma unroll
        for (int nf = 0; nf < 8; nf++)
            #pragma unroll
            for (int r = 0; r < 4; r++) sacc[nf][r] = 0.f;

        #pragma unroll
        for (int ks = 0; ks < 4; ++ks) {
            #pragma unroll
            for (int nf = 0; nf < 8; ++nf) {
                uint32_t bh2[2], bl2[2];
                const uint32_t ko = nf * 8 * ASTR + ks * 32 + kbrow;
                ldsm_x2(bh2, sb + A_KHI + ko);
                ldsm_x2(bl2, sb + A_KLO + ko);
                mma16816(sacc[nf], qah[ks], bh2);
                mma16816(sacc[nf], qal[ks], bh2);
                mma16816(sacc[nf], qah[ks], bl2);
            }
        }

        // ---- online softmax (exp2 domain) ----
        float rm0 = -1e30f, rm1 = -1e30f;
        #pragma unroll
        for (int nf = 0; nf < 8; nf++) {
            rm0 = fmaxf(rm0, fmaxf(sacc[nf][0], sacc[nf][1]));
            rm1 = fmaxf(rm1, fmaxf(sacc[nf][2], sacc[nf][3]));
        }
        rm0 = fmaxf(rm0, __shfl_xor_sync(0xffffffffu, rm0, 1));
        rm0 = fmaxf(rm0, __shfl_xor_sync(0xffffffffu, rm0, 2));
        rm1 = fmaxf(rm1, __shfl_xor_sync(0xffffffffu, rm1, 1));
        rm1 = fmaxf(rm1, __shfl_xor_sync(0xffffffffu, rm1, 2));
        const float mn0 = fmaxf(m0, rm0), mn1 = fmaxf(m1, rm1);
        const float alpha0 = exp2fast(m0 - mn0);
        const float alpha1 = exp2fast(m1 - mn1);
        m0 = mn0; m1 = mn1;

        uint32_t pahi[4][4], palo[4][4];
        float rs0 = 0.f, rs1 = 0.f;
        #pragma unroll
        for (int nf = 0; nf < 8; nf++) {
            float p0 = exp2fast(sacc[nf][0] - mn0);
            float p1 = exp2fast(sacc[nf][1] - mn0);
            float p2 = exp2fast(sacc[nf][2] - mn1);
            float p3 = exp2fast(sacc[nf][3] - mn1);
            rs0 += p0 + p1;
            rs1 += p2 + p3;
            const int ks = nf >> 1, hf = (nf & 1) * 2;
            split2(p0, p1, pahi[ks][hf],     palo[ks][hf]);
            split2(p2, p3, pahi[ks][hf + 1], palo[ks][hf + 1]);
        }
        rs0 += __shfl_xor_sync(0xffffffffu, rs0, 1);
        rs0 += __shfl_xor_sync(0xffffffffu, rs0, 2);
        rs1 += __shfl_xor_sync(0xffffffffu, rs1, 1);
        rs1 += __shfl_xor_sync(0xffffffffu, rs1, 2);
        l0 = l0 * alpha0 + rs0;
        l1 = l1 * alpha1 + rs1;

        #pragma unroll
        for (int nf = 0; nf < 8; nf++) {
            o[nf][0] *= alpha0; o[nf][1] *= alpha0;
            o[nf][2] *= alpha1; o[nf][3] *= alpha1;
        }

        // ---- O += P * V (3-pass hi/lo), V frags via ldmatrix.trans ----
        #pragma unroll
        for (int ks = 0; ks < 4; ++ks) {
            #pragma unroll
            for (int nf = 0; nf < 8; ++nf) {
                uint32_t bh2[2], bl2[2];
                const uint32_t vo = ks * 16 * ASTR + vbrow + nf * 16;
                ldsm_x2t(bh2, sb + A_VHI + vo);
                ldsm_x2t(bl2, sb + A_VLO + vo);
                mma16816(o[nf], pahi[ks], bh2);
                mma16816(o[nf], palo[ks], bh2);
                mma16816(o[nf], pahi[ks], bl2);
            }
        }
    }

    // ---- epilogue: normalize, store merged [B, S, H*Dk] ----
    const float i0 = 1.0f / l0;
    const float i1 = 1.0f / l1;
    const int r0 = qt * 64 + warp * 16 + (lane >> 2);
    #pragma unroll
    for (int nf = 0; nf < 8; nf++) {
        const int col = h * 64 + nf * 8 + (lane & 3) * 2;
        *(float2*)(outA + (size_t)(b * S_ + r0) * DM + col) =
            make_float2(o[nf][0] * i0, o[nf][1] * i0);
        *(float2*)(outA + (size_t)(b * S_ + r0 + 8) * DM + col) =
            make_float2(o[nf][2] * i1, o[nf][3] * i1);
    }
}

// ---------------------------------------------------------------------------
extern "C" void kernel_launch(void* const* d_in, const int* in_sizes, int n_in,
                              void* d_out, int out_size)
{
    const float* q  = (const float*)d_in[0];
    const float* k  = (const float*)d_in[1];
    const float* v  = (const float*)d_in[2];
    const float* Wq = (const float*)d_in[3];
    const float* bq = (const float*)d_in[4];
    const float* Wk = (const float*)d_in[5];
    const float* bk = (const float*)d_in[6];
    const float* Wv = (const float*)d_in[7];
    const float* bv = (const float*)d_in[8];
    const float* Wo = (const float*)d_in[9];
    const float* bo = (const float*)d_in[10];
    float* out = (float*)d_out;

    float *gQ, *gK, *gV, *gA;
    cudaGetSymbolAddress((void**)&gQ, g_Q);
    cudaGetSymbolAddress((void**)&gK, g_K);
    cudaGetSymbolAddress((void**)&gV, g_V);
    cudaGetSymbolAddress((void**)&gA, g_attn);

    cudaFuncSetAttribute(attn_mma,
        cudaFuncAttributeMaxDynamicSharedMemorySize, ATTN_SMEM);

    dim3 gg(DM / 128, M_ / 128);   // (8, 64)
    gemm_mma<<<gg, 256>>>(q, Wq, bq, gQ, 1);
    gemm_mma<<<gg, 256>>>(k, Wk, bk, gK, 1);
    gemm_mma<<<gg, 256>>>(v, Wv, bv, gV, 1);
    attn_mma<<<dim3(S_ / 64, H_, B_), 128, ATTN_SMEM>>>(gQ, gK, gV, gA);
    gemm_mma<<<gg, 256>>>(gA, Wo, bo, out, 0);
}

// round 8
// speedup vs baseline: 1.2942x; 1.2942x over previous
#include <cuda_runtime.h>
#include <cuda_bf16.h>
#include <math_constants.h>
#include <cstdint>

#define B_  4
#define H_  16
#define S_  2048
#define DM  1024
#define DK  64
#define M_  (B_*S_)

// ---------------- scratch (device globals; no allocation allowed) ----------
__device__ float g_Q[M_*DM];
__device__ float g_K[M_*DM];
__device__ float g_V[M_*DM];
__device__ float g_attn[M_*DM];

__device__ __forceinline__ uint32_t smem_u32(const void* p) {
    uint32_t a;
    asm("{ .reg .u64 t; cvta.to.shared.u64 t, %1; cvt.u32.u64 %0, t; }"
        : "=r"(a) : "l"(p));
    return a;
}
__device__ __forceinline__ void ldsm_x4(uint32_t r[4], uint32_t addr) {
    asm volatile("ldmatrix.sync.aligned.m8n8.x4.shared.b16 {%0,%1,%2,%3}, [%4];"
        : "=r"(r[0]), "=r"(r[1]), "=r"(r[2]), "=r"(r[3]) : "r"(addr));
}
__device__ __forceinline__ void ldsm_x4t(uint32_t r[4], uint32_t addr) {
    asm volatile("ldmatrix.sync.aligned.m8n8.x4.trans.shared.b16 {%0,%1,%2,%3}, [%4];"
        : "=r"(r[0]), "=r"(r[1]), "=r"(r[2]), "=r"(r[3]) : "r"(addr));
}
__device__ __forceinline__ void mma16816(float d[4], const uint32_t a[4],
                                         const uint32_t b[2]) {
    asm volatile(
        "mma.sync.aligned.m16n8k16.row.col.f32.bf16.bf16.f32 "
        "{%0,%1,%2,%3}, {%4,%5,%6,%7}, {%8,%9}, {%0,%1,%2,%3};"
        : "+f"(d[0]), "+f"(d[1]), "+f"(d[2]), "+f"(d[3])
        : "r"(a[0]), "r"(a[1]), "r"(a[2]), "r"(a[3]), "r"(b[0]), "r"(b[1]));
}

__device__ __forceinline__ uint32_t pk_bf2(float x, float y) {
    __nv_bfloat162 h = __floats2bfloat162_rn(x, y);
    return *reinterpret_cast<uint32_t*>(&h);
}
__device__ __forceinline__ void split2(float x, float y,
                                       uint32_t& hi, uint32_t& lo) {
    __nv_bfloat162 h2 = __floats2bfloat162_rn(x, y);
    float2 hf = __bfloat1622float2(h2);
    __nv_bfloat162 l2 = __floats2bfloat162_rn(x - hf.x, y - hf.y);
    hi = *reinterpret_cast<uint32_t*>(&h2);
    lo = *reinterpret_cast<uint32_t*>(&l2);
}
__device__ __forceinline__ void split8(float4 v0, float4 v1,
                                       uint4& hi, uint4& lo) {
    float h[8], f[8] = {v0.x, v0.y, v0.z, v0.w, v1.x, v1.y, v1.z, v1.w};
    float l[8];
    #pragma unroll
    for (int i = 0; i < 8; i++) {
        __nv_bfloat16 hb = __float2bfloat16_rn(f[i]);
        h[i] = __bfloat162float(hb);
        l[i] = f[i] - h[i];
    }
    hi = make_uint4(pk_bf2(h[0],h[1]), pk_bf2(h[2],h[3]),
                    pk_bf2(h[4],h[5]), pk_bf2(h[6],h[7]));
    lo = make_uint4(pk_bf2(l[0],l[1]), pk_bf2(l[2],l[3]),
                    pk_bf2(l[4],l[5]), pk_bf2(l[6],l[7]));
}

// Fast exp2 on FMA pipe (no MUFU).
__device__ __forceinline__ float exp2fast(float x) {
    x = fmaxf(x, -126.0f);
    float z = x + 12582912.0f;
    int   k = __float_as_int(z) - 0x4B400000;
    float f = x - (z - 12582912.0f);
    float p = fmaf(0.00133336f, f, 0.00961813f);
    p = fmaf(p, f, 0.05550411f);
    p = fmaf(p, f, 0.24022651f);
    p = fmaf(p, f, 0.69314718f);
    p = fmaf(p, f, 1.0f);
    return __int_as_float(__float_as_int(p) + (k << 23));
}

// ---------------------------------------------------------------------------
// Tensor-core GEMM: out = A*W^T + bias. R4 structure, restructured inner loop:
// hi/lo fragments loaded ONCE per k-step (x4 B loads), 3 passes from regs.
// ---------------------------------------------------------------------------
#define TSTR   80
#define TILEB  (128*TSTR)
#define AT_HI  0
#define AT_LO  TILEB
#define WT_HI  (2*TILEB)
#define WT_LO  (3*TILEB)

__global__ __launch_bounds__(256)
void gemm_mma(const float* __restrict__ A, const float* __restrict__ W,
              const float* __restrict__ bias, float* __restrict__ out,
              int split_heads)
{
    __shared__ __align__(16) char sm[4*TILEB];
    const uint32_t sb = smem_u32(sm);

    const int tid = threadIdx.x;
    const int m0  = blockIdx.y << 7;
    const int n0  = blockIdx.x << 7;
    const int warp = tid >> 5;
    const int lane = tid & 31;
    const int wm = (warp >> 2) * 64;
    const int wn = (warp & 3) * 32;

    const uint32_t arow  = (lane & 15) * TSTR + (lane >> 4) * 16;
    const uint32_t brow4 = (lane & 7) * TSTR + ((lane >> 3) & 1) * 16
                         + (lane >> 4) * (8 * TSTR);

    const int lrow = tid >> 1;
    const int lcg  = (tid & 1) * 16;
    const float* Ag = A + (size_t)(m0 + lrow) * DM + lcg;
    const float* Wg = W + (size_t)(n0 + lrow) * DM + lcg;
    char* smArow = sm + lrow * TSTR + lcg * 2;
    char* smWrow = smArow;

    float acc[4][4][4];
    #pragma unroll
    for (int i = 0; i < 4; i++)
        #pragma unroll
        for (int j = 0; j < 4; j++)
            #pragma unroll
            for (int r = 0; r < 4; r++) acc[i][j][r] = 0.f;

    float4 ra0 = *(const float4*)(Ag);      float4 ra1 = *(const float4*)(Ag + 4);
    float4 ra2 = *(const float4*)(Ag + 8);  float4 ra3 = *(const float4*)(Ag + 12);
    float4 rw0 = *(const float4*)(Wg);      float4 rw1 = *(const float4*)(Wg + 4);
    float4 rw2 = *(const float4*)(Wg + 8);  float4 rw3 = *(const float4*)(Wg + 12);

    for (int c = 0; c < DM / 32; ++c) {
        __syncthreads();
        uint4 hi, lo;
        split8(ra0, ra1, hi, lo);
        *(uint4*)(smArow + AT_HI)      = hi;  *(uint4*)(smArow + AT_LO)      = lo;
        split8(ra2, ra3, hi, lo);
        *(uint4*)(smArow + AT_HI + 16) = hi;  *(uint4*)(smArow + AT_LO + 16) = lo;
        split8(rw0, rw1, hi, lo);
        *(uint4*)(smWrow + WT_HI)      = hi;  *(uint4*)(smWrow + WT_LO)      = lo;
        split8(rw2, rw3, hi, lo);
        *(uint4*)(smWrow + WT_HI + 16) = hi;  *(uint4*)(smWrow + WT_LO + 16) = lo;
        __syncthreads();

        if (c < DM / 32 - 1) {
            const float* An = Ag + (c + 1) * 32;
            const float* Wn = Wg + (c + 1) * 32;
            ra0 = *(const float4*)(An);      ra1 = *(const float4*)(An + 4);
            ra2 = *(const float4*)(An + 8);  ra3 = *(const float4*)(An + 12);
            rw0 = *(const float4*)(Wn);      rw1 = *(const float4*)(Wn + 4);
            rw2 = *(const float4*)(Wn + 8);  rw3 = *(const float4*)(Wn + 12);
        }

        #pragma unroll
        for (int ks = 0; ks < 2; ++ks) {
            uint32_t ah[4][4], al[4][4], bh[2][4], bl[2][4];
            #pragma unroll
            for (int mt = 0; mt < 4; ++mt) {
                const uint32_t ao = (wm + mt*16) * TSTR + ks*32 + arow;
                ldsm_x4(ah[mt], sb + AT_HI + ao);
                ldsm_x4(al[mt], sb + AT_LO + ao);
            }
            #pragma unroll
            for (int np = 0; np < 2; ++np) {
                const uint32_t bo = (wn + np*16) * TSTR + ks*32 + brow4;
                ldsm_x4(bh[np], sb + WT_HI + bo);
                ldsm_x4(bl[np], sb + WT_LO + bo);
            }
            #pragma unroll
            for (int mt = 0; mt < 4; ++mt)
                #pragma unroll
                for (int nt = 0; nt < 4; ++nt) {
                    const uint32_t* bhf = &bh[nt >> 1][(nt & 1) * 2];
                    const uint32_t* blf = &bl[nt >> 1][(nt & 1) * 2];
                    mma16816(acc[mt][nt], ah[mt], bhf);
                    mma16816(acc[mt][nt], al[mt], bhf);
                    mma16816(acc[mt][nt], ah[mt], blf);
                }
        }
    }

    #pragma unroll
    for (int mt = 0; mt < 4; ++mt) {
        #pragma unroll
        for (int nt = 0; nt < 4; ++nt) {
            const int col = n0 + wn + nt*8 + (lane & 3) * 2;
            const float2 bv = *(const float2*)(bias + col);
            #pragma unroll
            for (int half = 0; half < 2; ++half) {
                const int row = m0 + wm + mt*16 + (lane >> 2) + half * 8;
                float2 o2 = make_float2(acc[mt][nt][2*half]   + bv.x,
                                        acc[mt][nt][2*half+1] + bv.y);
                size_t idx;
                if (split_heads) {
                    const int head = col >> 6;
                    const int bi = row >> 11, si = row & (S_ - 1);
                    idx = (((size_t)(bi * H_ + head)) * S_ + si) * DK + (col & 63);
                } else {
                    idx = (size_t)row * DM + col;
                }
                *(float2*)(out + idx) = o2;
            }
        }
    }
}

// ---------------------------------------------------------------------------
// Tensor-core flash attention (R4 config: 128 q-rows, 256 thr, 72KB smem)
// + Q fragments hoisted + x4 B-operand ldmatrix (half the LDSM instructions).
// ---------------------------------------------------------------------------
#define ASTR   144
#define A_QHI  0
#define A_QLO  18432
#define A_KHI  36864
#define A_KLO  46080
#define A_VHI  55296
#define A_VLO  64512
#define ATTN_SMEM 73728

extern __shared__ char dynsm[];

__global__ __launch_bounds__(256, 1)
void attn_mma(const float* __restrict__ Qh, const float* __restrict__ Kh,
              const float* __restrict__ Vh, float* __restrict__ outA)
{
    const uint32_t sb = smem_u32(dynsm);
    const int tid = threadIdx.x;
    const int lane = tid & 31;
    const int warp = tid >> 5;
    const int qt = blockIdx.x, h = blockIdx.y, b = blockIdx.z;

    const size_t bh = (size_t)(b * H_ + h) * S_ * DK;
    const float* Qb = Qh + bh + (size_t)qt * 128 * DK;
    const float* Kb = Kh + bh;
    const float* Vb = Vh + bh;

    // ---- Q: load, scale by 0.125*log2(e), hi/lo split, store to smem ----
    {
        const int row = tid >> 1;
        const int c0  = (tid & 1) * 32;
        const float* g = Qb + row * DK + c0;
        char* s = dynsm + row * ASTR + c0 * 2;
        const float sc = 0.1803368801f;
        #pragma unroll
        for (int j = 0; j < 4; j++) {
            float4 v0 = *(const float4*)(g + j*8);
            float4 v1 = *(const float4*)(g + j*8 + 4);
            v0.x *= sc; v0.y *= sc; v0.z *= sc; v0.w *= sc;
            v1.x *= sc; v1.y *= sc; v1.z *= sc; v1.w *= sc;
            uint4 hi, lo; split8(v0, v1, hi, lo);
            *(uint4*)(s + A_QHI + j*16) = hi;
            *(uint4*)(s + A_QLO + j*16) = lo;
        }
    }
    __syncthreads();

    // ---- hoist Q fragments (loop-invariant) ----
    uint32_t qah[4][4], qal[4][4];
    {
        const uint32_t qrow = (warp * 16 + (lane & 15)) * ASTR + (lane >> 4) * 16;
        #pragma unroll
        for (int ks = 0; ks < 4; ++ks) {
            ldsm_x4(qah[ks], sb + A_QHI + qrow + ks * 32);
            ldsm_x4(qal[ks], sb + A_QLO + qrow + ks * 32);
        }
    }

    float m0 = -1e30f, m1 = -1e30f, l0 = 0.f, l1 = 0.f;
    float o[8][4];
    #pragma unroll
    for (int nf = 0; nf < 8; nf++)
        #pragma unroll
        for (int r = 0; r < 4; r++) o[nf][r] = 0.f;

    const int krow = tid >> 2;
    const int kcg  = (tid & 3) * 16;
    char* kvs = dynsm + krow * ASTR + kcg * 2;

    float4 kf[4], vf[4];
    {
        const float* kg = Kb + (size_t)krow * DK + kcg;
        const float* vg = Vb + (size_t)krow * DK + kcg;
        #pragma unroll
        for (int j = 0; j < 4; j++) {
            kf[j] = *(const float4*)(kg + j*4);
            vf[j] = *(const float4*)(vg + j*4);
        }
    }

    // x4 B-operand lane address maps (conflict-free: 144*k mod 128 walks banks)
    const uint32_t kbrow4 = (lane & 7) * ASTR + ((lane >> 3) & 1) * 16
                          + (lane >> 4) * (8 * ASTR);
    const uint32_t vbrow4 = (lane & 15) * ASTR + (lane >> 4) * 16;

    for (int kt = 0; kt < S_ / 64; ++kt) {
        __syncthreads();
        {
            uint4 hi, lo;
            split8(kf[0], kf[1], hi, lo);
            *(uint4*)(kvs + A_KHI)      = hi;  *(uint4*)(kvs + A_KLO)      = lo;
            split8(kf[2], kf[3], hi, lo);
            *(uint4*)(kvs + A_KHI + 16) = hi;  *(uint4*)(kvs + A_KLO + 16) = lo;
            split8(vf[0], vf[1], hi, lo);
            *(uint4*)(kvs + A_VHI)      = hi;  *(uint4*)(kvs + A_VLO)      = lo;
            split8(vf[2], vf[3], hi, lo);
            *(uint4*)(kvs + A_VHI + 16) = hi;  *(uint4*)(kvs + A_VLO + 16) = lo;
        }
        __syncthreads();

        if (kt < S_ / 64 - 1) {
            const float* kg = Kb + (size_t)((kt+1)*64 + krow) * DK + kcg;
            const float* vg = Vb + (size_t)((kt+1)*64 + krow) * DK + kcg;
            #pragma unroll
            for (int j = 0; j < 4; j++) {
                kf[j] = *(const float4*)(kg + j*4);
                vf[j] = *(const float4*)(vg + j*4);
            }
        }

        // ---- scores S[16q x 64k] (3-pass hi/lo; x4 K loads) ----
        float sacc[8][4];
        #pragma unroll
        for (int nf = 0; nf < 8; nf++)
            #pragma unroll
            for (int r = 0; r < 4; r++) sacc[nf][r] = 0.f;

        #pragma unroll
        for (int ks = 0; ks < 4; ++ks) {
            #pragma unroll
            for (int np = 0; np < 4; ++np) {     // key pair: nf = 2np, 2np+1
                uint32_t bh4[4], bl4[4];
                const uint32_t ko = np * 16 * ASTR + ks * 32 + kbrow4;
                ldsm_x4(bh4, sb + A_KHI + ko);
                ldsm_x4(bl4, sb + A_KLO + ko);
                mma16816(sacc[2*np],   qah[ks], &bh4[0]);
                mma16816(sacc[2*np],   qal[ks], &bh4[0]);
                mma16816(sacc[2*np],   qah[ks], &bl4[0]);
                mma16816(sacc[2*np+1], qah[ks], &bh4[2]);
                mma16816(sacc[2*np+1], qal[ks], &bh4[2]);
                mma16816(sacc[2*np+1], qah[ks], &bl4[2]);
            }
        }

        // ---- online softmax (exp2 domain) ----
        float rm0 = -1e30f, rm1 = -1e30f;
        #pragma unroll
        for (int nf = 0; nf < 8; nf++) {
            rm0 = fmaxf(rm0, fmaxf(sacc[nf][0], sacc[nf][1]));
            rm1 = fmaxf(rm1, fmaxf(sacc[nf][2], sacc[nf][3]));
        }
        rm0 = fmaxf(rm0, __shfl_xor_sync(0xffffffffu, rm0, 1));
        rm0 = fmaxf(rm0, __shfl_xor_sync(0xffffffffu, rm0, 2));
        rm1 = fmaxf(rm1, __shfl_xor_sync(0xffffffffu, rm1, 1));
        rm1 = fmaxf(rm1, __shfl_xor_sync(0xffffffffu, rm1, 2));
        const float mn0 = fmaxf(m0, rm0), mn1 = fmaxf(m1, rm1);
        const float alpha0 = exp2fast(m0 - mn0);
        const float alpha1 = exp2fast(m1 - mn1);
        m0 = mn0; m1 = mn1;

        uint32_t pahi[4][4], palo[4][4];
        float rs0 = 0.f, rs1 = 0.f;
        #pragma unroll
        for (int nf = 0; nf < 8; nf++) {
            float p0 = exp2fast(sacc[nf][0] - mn0);
            float p1 = exp2fast(sacc[nf][1] - mn0);
            float p2 = exp2fast(sacc[nf][2] - mn1);
            float p3 = exp2fast(sacc[nf][3] - mn1);
            rs0 += p0 + p1;
            rs1 += p2 + p3;
            const int ks = nf >> 1, hf = (nf & 1) * 2;
            split2(p0, p1, pahi[ks][hf],     palo[ks][hf]);
            split2(p2, p3, pahi[ks][hf + 1], palo[ks][hf + 1]);
        }
        rs0 += __shfl_xor_sync(0xffffffffu, rs0, 1);
        rs0 += __shfl_xor_sync(0xffffffffu, rs0, 2);
        rs1 += __shfl_xor_sync(0xffffffffu, rs1, 1);
        rs1 += __shfl_xor_sync(0xffffffffu, rs1, 2);
        l0 = l0 * alpha0 + rs0;
        l1 = l1 * alpha1 + rs1;

        #pragma unroll
        for (int nf = 0; nf < 8; nf++) {
            o[nf][0] *= alpha0; o[nf][1] *= alpha0;
            o[nf][2] *= alpha1; o[nf][3] *= alpha1;
        }

        // ---- O += P * V (3-pass hi/lo; x4 trans V loads) ----
        #pragma unroll
        for (int ks = 0; ks < 4; ++ks) {
            #pragma unroll
            for (int np = 0; np < 4; ++np) {     // dk pair: nf = 2np, 2np+1
                uint32_t vh4[4], vl4[4];
                const uint32_t vo = ks * 16 * ASTR + vbrow4 + np * 32;
                ldsm_x4t(vh4, sb + A_VHI + vo);
                ldsm_x4t(vl4, sb + A_VLO + vo);
                mma16816(o[2*np],   pahi[ks], &vh4[0]);
                mma16816(o[2*np],   palo[ks], &vh4[0]);
                mma16816(o[2*np],   pahi[ks], &vl4[0]);
                mma16816(o[2*np+1], pahi[ks], &vh4[2]);
                mma16816(o[2*np+1], palo[ks], &vh4[2]);
                mma16816(o[2*np+1], pahi[ks], &vl4[2]);
            }
        }
    }

    // ---- epilogue ----
    const float i0 = 1.0f / l0;
    const float i1 = 1.0f / l1;
    const int r0 = qt * 128 + warp * 16 + (lane >> 2);
    #pragma unroll
    for (int nf = 0; nf < 8; nf++) {
        const int col = h * 64 + nf * 8 + (lane & 3) * 2;
        *(float2*)(outA + (size_t)(b * S_ + r0) * DM + col) =
            make_float2(o[nf][0] * i0, o[nf][1] * i0);
        *(float2*)(outA + (size_t)(b * S_ + r0 + 8) * DM + col) =
            make_float2(o[nf][2] * i1, o[nf][3] * i1);
    }
}

// ---------------------------------------------------------------------------
extern "C" void kernel_launch(void* const* d_in, const int* in_sizes, int n_in,
                              void* d_out, int out_size)
{
    const float* q  = (const float*)d_in[0];
    const float* k  = (const float*)d_in[1];
    const float* v  = (const float*)d_in[2];
    const float* Wq = (const float*)d_in[3];
    const float* bq = (const float*)d_in[4];
    const float* Wk = (const float*)d_in[5];
    const float* bk = (const float*)d_in[6];
    const float* Wv = (const float*)d_in[7];
    const float* bv = (const float*)d_in[8];
    const float* Wo = (const float*)d_in[9];
    const float* bo = (const float*)d_in[10];
    float* out = (float*)d_out;

    float *gQ, *gK, *gV, *gA;
    cudaGetSymbolAddress((void**)&gQ, g_Q);
    cudaGetSymbolAddress((void**)&gK, g_K);
    cudaGetSymbolAddress((void**)&gV, g_V);
    cudaGetSymbolAddress((void**)&gA, g_attn);

    cudaFuncSetAttribute(attn_mma,
        cudaFuncAttributeMaxDynamicSharedMemorySize, ATTN_SMEM);

    dim3 gg(DM / 128, M_ / 128);   // (8, 64)
    gemm_mma<<<gg, 256>>>(q, Wq, bq, gQ, 1);
    gemm_mma<<<gg, 256>>>(k, Wk, bk, gK, 1);
    gemm_mma<<<gg, 256>>>(v, Wv, bv, gV, 1);
    attn_mma<<<dim3(S_ / 128, H_, B_), 256, ATTN_SMEM>>>(gQ, gK, gV, gA);
    gemm_mma<<<gg, 256>>>(gA, Wo, bo, out, 0);
}